// round 14
// baseline (speedup 1.0000x reference)
#include <cuda_runtime.h>
#include <cuda_fp16.h>
#include <math.h>
#include <stdint.h>

// Problem constants
#define BB   16
#define SS   600
#define EE   300
#define HH   512
#define NCC  2
#define DD   180000L
#define TT   3

#define KAH  320
#define KPH  640

// fused W1 kernel tiling. PROTECTED: DSLICE=320 @ 2 CTA/SM (R13 win).
// R10 lesson: never shrink below 256 (halved MLP regressed 23%).
#define DSLICE 320
#define HCHUNK 32
#define NCHUNK (HH / HCHUNK)
#define NDBLK  ((int)((DD + DSLICE - 1) / DSLICE))   // 563

// ---------------- scratch (device globals; zero-initialized) -----------------
__device__ float g_Wx [BB * SS * EE];
__device__ float g_Praw[BB * SS * SS];
__device__ float g_n1a[BB * HH];
__device__ float g_n1b[BB * HH];
__device__ float g_n2a[BB * NCC];
__device__ float g_n2b[BB * NCC];
__device__ float g_g1 [BB * HH];          // zero-based accumulator (reset by epilogue)
__device__ int   g_ctr;                   // fused_w1 completion counter
__device__ __half g_xh  [(size_t)BB * SS * KAH];
__device__ __half g_xTh [(size_t)BB * 320 * KPH];
__device__ __half g_g0h [(size_t)BB * SS * KAH];
__device__ __half g_Ph  [(size_t)BB * SS * KPH];
__device__ __half g_W0h [(size_t)EE * KAH];
__device__ __half g_n0h [(size_t)BB * DD + 1024];
__device__ __half g_n1h [BB * HH];

// ---------------- helpers -----------------------------------------------------
__device__ __forceinline__ uint32_t smem_u32(const void* p) {
    uint32_t a;
    asm("{ .reg .u64 t; cvta.to.shared.u64 t, %1; cvt.u32.u64 %0, t; }" : "=r"(a) : "l"(p));
    return a;
}
__device__ __forceinline__ void ldm_x4(uint32_t* r, uint32_t addr) {
    asm volatile("ldmatrix.sync.aligned.m8n8.x4.shared.b16 {%0,%1,%2,%3}, [%4];"
                 : "=r"(r[0]), "=r"(r[1]), "=r"(r[2]), "=r"(r[3]) : "r"(addr));
}
__device__ __forceinline__ void ldm_x4_t(uint32_t* r, uint32_t addr) {
    asm volatile("ldmatrix.sync.aligned.m8n8.x4.trans.shared.b16 {%0,%1,%2,%3}, [%4];"
                 : "=r"(r[0]), "=r"(r[1]), "=r"(r[2]), "=r"(r[3]) : "r"(addr));
}
__device__ __forceinline__ void mma16816(float* c, const uint32_t* a, const uint32_t* b) {
    asm volatile(
        "mma.sync.aligned.m16n8k16.row.col.f32.f16.f16.f32 "
        "{%0,%1,%2,%3}, {%4,%5,%6,%7}, {%8,%9}, {%0,%1,%2,%3};"
        : "+f"(c[0]), "+f"(c[1]), "+f"(c[2]), "+f"(c[3])
        : "r"(a[0]), "r"(a[1]), "r"(a[2]), "r"(a[3]), "r"(b[0]), "r"(b[1]));
}
__device__ __forceinline__ void cp_async16(uint32_t dst, const void* src, int bytes) {
    asm volatile("cp.async.cg.shared.global [%0], [%1], 16, %2;"
                 :: "r"(dst), "l"(src), "r"(bytes));
}
__device__ __forceinline__ void cp_commit() {
    asm volatile("cp.async.commit_group;");
}
template <int N>
__device__ __forceinline__ void cp_wait() {
    asm volatile("cp.async.wait_group %0;" :: "n"(N));
}

// ============ fused per-step W1 kernel (DSLICE=320 + fused tanh epilogue) ====
// Streams W1 (fp32) once per step:
//   g0h <- fp16((Wx + n1 @ W1) * scale)
//   g1  += n0flat @ W1^T  (zero-based; bias applied in last-block epilogue)
// Last block: n1n/n1h = tanh(g1 + b1 + n2c@W2), resets g1 and counter.
__global__ __launch_bounds__(256, 2)
void fused_w1_kernel(const float* __restrict__ W1,
                     const __half* __restrict__ n1h_in,
                     const __half* __restrict__ n0h,
                     const float* __restrict__ Wx,
                     float* __restrict__ g1,
                     __half* __restrict__ g0h,
                     const float* __restrict__ b1,
                     const float* __restrict__ W2,
                     const float* __restrict__ n2c,
                     float* __restrict__ n1n,
                     __half* __restrict__ n1h_out,
                     float scale)
{
    __shared__ __align__(16) __half tF[HCHUNK][DSLICE + 8];
    __shared__ float g1buf[HCHUNK][17];

    const int t = threadIdx.x, lane = t & 31, wid = t >> 5;
    const long d0 = (long)blockIdx.x * DSLICE;

    uint4 pre[10];

    auto issue_loads = [&](int hc) {
#pragma unroll
        for (int i = 0; i < 10; ++i) {
            int f = t + i * 256;
            int row = f / 80, c4 = f % 80;
            long d = d0 + (long)c4 * 4;
            if (d + 4 <= DD)
                pre[i] = *(const uint4*)(W1 + (long)(hc * HCHUNK + row) * DD + d);
            else
                pre[i] = make_uint4(0, 0, 0, 0);
        }
    };
    auto store_tiles = [&]() {
#pragma unroll
        for (int i = 0; i < 10; ++i) {
            int f = t + i * 256;
            int row = f / 80, c4 = f % 80;
            float4 v = *(float4*)&pre[i];
            __half h[4];
            h[0] = __float2half_rn(v.x);
            h[1] = __float2half_rn(v.y);
            h[2] = __float2half_rn(v.z);
            h[3] = __float2half_rn(v.w);
            *(uint2*)&tF[row][c4 * 4] = *(uint2*)h;
        }
    };

    float accg0[10][4] = {};

    issue_loads(0);
    store_tiles();
    for (int i = t; i < HCHUNK * 17; i += 256) ((float*)g1buf)[i] = 0.f;
    __syncthreads();

    for (int hc = 0; hc < NCHUNK; ++hc) {
        if (hc + 1 < NCHUNK) issue_loads(hc + 1);

        if (wid < 4) {
            const int tr_r = lane & 15, tr_c = (lane >> 4) * 8;
            const int ar = lane >> 2, ac = (lane & 3) * 2;
#pragma unroll
            for (int ks = 0; ks < 2; ++ks) {
                int kb = hc * HCHUNK + ks * 16;
                uint32_t ah[4];
                ah[0] = *(const uint32_t*)(n1h_in + ar * HH + kb + ac);
                ah[1] = *(const uint32_t*)(n1h_in + (ar + 8) * HH + kb + ac);
                ah[2] = *(const uint32_t*)(n1h_in + ar * HH + kb + ac + 8);
                ah[3] = *(const uint32_t*)(n1h_in + (ar + 8) * HH + kb + ac + 8);
#pragma unroll
                for (int q = 0; q < 5; ++q) {
                    uint32_t bf[4];
                    ldm_x4_t(bf, smem_u32(&tF[ks * 16 + tr_r][wid * 80 + q * 16 + tr_c]));
                    mma16816(accg0[q * 2],     ah, &bf[0]);
                    mma16816(accg0[q * 2 + 1], ah, &bf[2]);
                }
            }
        } else {
            const int w = wid - 4;
            const int a_r = lane & 15, a_c = (lane >> 4) * 8;
            float acc1[2][2][4] = {};
#pragma unroll
            for (int ks = 0; ks < 5; ++ks) {
                long dk = d0 + w * 80 + ks * 16;
                uint32_t bh[2][2];
#pragma unroll
                for (int nt = 0; nt < 2; ++nt) {
                    long baddr = (long)(nt * 8 + (lane >> 2)) * DD + dk + (lane & 3) * 2;
                    bh[nt][0] = *(const uint32_t*)(n0h + baddr);
                    bh[nt][1] = *(const uint32_t*)(n0h + baddr + 8);
                }
#pragma unroll
                for (int mt = 0; mt < 2; ++mt) {
                    uint32_t af[4];
                    ldm_x4(af, smem_u32(&tF[mt * 16 + a_r][w * 80 + ks * 16 + a_c]));
#pragma unroll
                    for (int nt = 0; nt < 2; ++nt)
                        mma16816(acc1[mt][nt], af, bh[nt]);
                }
            }
            const int cr = lane >> 2, cc = (lane & 3) * 2;
#pragma unroll
            for (int mt = 0; mt < 2; ++mt)
#pragma unroll
                for (int nt = 0; nt < 2; ++nt) {
                    atomicAdd(&g1buf[mt * 16 + cr][nt * 8 + cc],         acc1[mt][nt][0]);
                    atomicAdd(&g1buf[mt * 16 + cr][nt * 8 + cc + 1],     acc1[mt][nt][1]);
                    atomicAdd(&g1buf[mt * 16 + cr + 8][nt * 8 + cc],     acc1[mt][nt][2]);
                    atomicAdd(&g1buf[mt * 16 + cr + 8][nt * 8 + cc + 1], acc1[mt][nt][3]);
                }
        }
        __syncthreads();

#pragma unroll
        for (int i = 0; i < 2; ++i) {
            int idx = t + i * 256;
            int h = idx >> 4, b = idx & 15;
            float v = g1buf[h][b];
            if (v != 0.f) atomicAdd(&g1[b * HH + hc * HCHUNK + h], v);
            g1buf[h][b] = 0.f;
        }
        if (hc + 1 < NCHUNK) store_tiles();
        __syncthreads();
    }

    // g0 epilogue: (Wx + acc) * scale -> fp16
    if (wid < 4) {
        const int ar = lane >> 2, cc = (lane & 3) * 2;
#pragma unroll
        for (int q = 0; q < 10; ++q) {
            int dn = wid * 80 + q * 8 + cc;
            long d = d0 + dn;
            if (d + 1 < DD) {
                int s = (int)(d / EE), e = (int)(d % EE);
#pragma unroll
                for (int half = 0; half < 2; ++half) {
                    int bb = ar + half * 8;
                    float2 wx = *(const float2*)(Wx + (long)bb * DD + d);
                    __half h[2];
                    h[0] = __float2half_rn((wx.x + accg0[q][half * 2])     * scale);
                    h[1] = __float2half_rn((wx.y + accg0[q][half * 2 + 1]) * scale);
                    *(uint32_t*)&g0h[((long)(bb * SS + s)) * KAH + e] = *(uint32_t*)h;
                }
            }
        }
    }

    // ---- last-block epilogue: n1 = tanh(g1 + b1 + n2c@W2); reset g1, counter
    __threadfence();
    __shared__ int is_last;
    if (t == 0) is_last = (atomicAdd(&g_ctr, 1) == NDBLK - 1) ? 1 : 0;
    __syncthreads();
    if (is_last) {
        for (int i = t; i < BB * HH; i += 256) {
            int b = i >> 9, h = i & (HH - 1);
            float v = tanhf(g1[i] + b1[h]
                            + n2c[b * NCC] * W2[h] + n2c[b * NCC + 1] * W2[HH + h]);
            n1n[i] = v;
            n1h_out[i] = __float2half_rn(v);
            g1[i] = 0.f;
        }
        __threadfence();
        if (t == 0) g_ctr = 0;
    }
}

// ---------------- pipelined HMMA GEMM (fp16): C = A · B^T --------------------
__global__ __launch_bounds__(256, 2)
void hmma_gemm_kernel(const __half* __restrict__ A,
                      const __half* __restrict__ B,
                      float* __restrict__ C,
                      __half* __restrict__ Ch,
                      int ldA, long bsA, int rowsA,
                      int ldB, long bsB, int rowsB,
                      int ldC, long bsC, int Mvalid, int Nvalid,
                      int ldCh, float ch_scale,
                      int kchunks)
{
    __shared__ __align__(16) __half As[2][128][40];
    __shared__ __align__(16) __half Bs[2][128][40];
    const int t = threadIdx.x, lane = t & 31, wid = t >> 5;
    const int wm = wid >> 2, wn = wid & 3;
    const int b = blockIdx.z, m0 = blockIdx.y * 128, n0 = blockIdx.x * 128;
    const __half* Ab = A + (long)b * bsA;
    const __half* Bb = B + (long)b * bsB;
    float acc[4][4][4] = {};

    const int l_row = t >> 2, l_q = t & 3;
    auto stage_in = [&](int ch, int buf) {
        long kg = (long)ch * 32 + l_q * 8;
#pragma unroll
        for (int i = 0; i < 2; ++i) {
            int row = l_row + i * 64;
            int ra = m0 + row, rb = n0 + row;
            int ca = (ra < rowsA) ? 16 : 0;
            int cb = (rb < rowsB) ? 16 : 0;
            if (ra >= rowsA) ra = 0;
            if (rb >= rowsB) rb = 0;
            cp_async16(smem_u32(&As[buf][row][l_q * 8]), Ab + (long)ra * ldA + kg, ca);
            cp_async16(smem_u32(&Bs[buf][row][l_q * 8]), Bb + (long)rb * ldB + kg, cb);
        }
    };

    stage_in(0, 0); cp_commit();
    if (kchunks > 1) { stage_in(1, 1); }
    cp_commit();

    const int a_lm = lane & 15;
    const int a_lk = (lane >> 4) * 8;
    const int b_ln = (lane & 7) + ((lane >> 4) & 1) * 8;
    const int b_lk = ((lane >> 3) & 1) * 8;

    for (int ch = 0; ch < kchunks; ++ch) {
        const int buf = ch & 1;
        cp_wait<1>();
        __syncthreads();
#pragma unroll
        for (int ks = 0; ks < 2; ++ks) {
            uint32_t af[4][4], bf[4][2];
#pragma unroll
            for (int mf = 0; mf < 4; ++mf)
                ldm_x4(af[mf], smem_u32(&As[buf][wm * 64 + mf * 16 + a_lm][ks * 16 + a_lk]));
#pragma unroll
            for (int nf2 = 0; nf2 < 2; ++nf2) {
                uint32_t r[4];
                ldm_x4(r, smem_u32(&Bs[buf][wn * 32 + nf2 * 16 + b_ln][ks * 16 + b_lk]));
                bf[nf2 * 2][0] = r[0];     bf[nf2 * 2][1] = r[1];
                bf[nf2 * 2 + 1][0] = r[2]; bf[nf2 * 2 + 1][1] = r[3];
            }
#pragma unroll
            for (int mf = 0; mf < 4; ++mf)
#pragma unroll
                for (int nf = 0; nf < 4; ++nf)
                    mma16816(acc[mf][nf], af[mf], bf[nf]);
        }
        __syncthreads();
        if (ch + 2 < kchunks) stage_in(ch + 2, buf);
        cp_commit();
    }

    const int mbase = m0 + wm * 64, nbase = n0 + wn * 32;
#pragma unroll
    for (int mf = 0; mf < 4; ++mf) {
#pragma unroll
        for (int nf = 0; nf < 4; ++nf) {
            int m = mbase + mf * 16 + (lane >> 2);
            int n = nbase + nf * 8 + (lane & 3) * 2;
            if (n < Nvalid) {
#pragma unroll
                for (int half = 0; half < 2; ++half) {
                    int mm = m + half * 8;
                    float v0 = acc[mf][nf][half * 2], v1 = acc[mf][nf][half * 2 + 1];
                    if (mm < Mvalid) {
                        if (C)
                            *(float2*)&C[(long)b * bsC + (long)mm * ldC + n] =
                                make_float2(v0, v1);
                        if (Ch) {
                            __half h[2];
                            h[0] = __float2half_rn(v0 * ch_scale);
                            h[1] = __float2half_rn(v1 * ch_scale);
                            *(uint32_t*)&Ch[(long)b * bsC + (long)mm * ldCh + n] =
                                *(uint32_t*)h;
                        }
                    }
                }
            }
        }
    }
}

// ---------------- conversions (merged x + W0) ---------------------------------
// gridDim.x = 640 + EE: first 640*BB handle x, rest handle W0 rows.
__global__ void conv_inputs_kernel(const float* __restrict__ x,
                                   const float* __restrict__ W0,
                                   __half* __restrict__ xh,
                                   __half* __restrict__ xTh,
                                   __half* __restrict__ W0h)
{
    int e = threadIdx.x;
    if (blockIdx.x < 640) {
        int s = blockIdx.x, b = blockIdx.y;
        if (s < SS) {
            float v = (e < EE) ? x[((long)b * SS + s) * EE + e] : 0.f;
            __half h = __float2half_rn(v);
            xh[((long)b * SS + s) * KAH + e] = h;
            xTh[((long)b * 320 + e) * KPH + s] = h;
        } else {
            xTh[((long)b * 320 + e) * KPH + s] = __float2half_rn(0.f);
        }
    } else if (blockIdx.y == 0) {
        int f = blockIdx.x - 640;
        float v = (e < EE) ? W0[f * EE + e] : 0.f;
        W0h[(long)f * KAH + e] = __float2half_rn(v);
    }
}

// ---------------- n2 update (g2): n2n = tanh(b2 + n1c @ W2^T) ----------------
__global__ void g2_kernel(const float* __restrict__ n1c, const float* __restrict__ W2,
                          const float* __restrict__ b2, float* __restrict__ n2n)
{
    int t = threadIdx.x;
    int wid = t >> 5, lane = t & 31;
    int b = wid >> 1, c = wid & 1;
    float s = 0.f;
    for (int h = lane; h < HH; h += 32)
        s += n1c[b * HH + h] * W2[c * HH + h];
#pragma unroll
    for (int off = 16; off > 0; off >>= 1)
        s += __shfl_down_sync(0xffffffffu, s, off);
    if (lane == 0) n2n[b * NCC + c] = tanhf(b2[c] + s);
}

__global__ void init_step0_kernel(const float* __restrict__ b1, const float* __restrict__ b2,
                                  float* __restrict__ n1n, float* __restrict__ n2n,
                                  __half* __restrict__ n1h)
{
    int b = blockIdx.x, h = threadIdx.x;
    float v = tanhf(b1[h]);
    n1n[b * HH + h] = v;
    n1h[b * HH + h] = __float2half_rn(v);
    if (h < NCC) n2n[b * NCC + h] = tanhf(b2[h]);
}

// ---------------- softmax: warp-per-row, fused fp16 conversion ---------------
__global__ __launch_bounds__(256)
void softmax_conv_kernel(const float* __restrict__ Praw, __half* __restrict__ Ph)
{
    const int w = threadIdx.x >> 5, lane = threadIdx.x & 31;
    const long r = (long)blockIdx.x * 8 + w;
    const float* p = Praw + r * SS;
    __half* out = Ph + r * KPH;

    float4 v[5];
    float mx = -INFINITY;
#pragma unroll
    for (int it = 0; it < 5; ++it) {
        int c = lane * 4 + it * 128;
        if (c < SS) {
            v[it] = *(const float4*)(p + c);
            mx = fmaxf(mx, fmaxf(fmaxf(v[it].x, v[it].y), fmaxf(v[it].z, v[it].w)));
        }
    }
#pragma unroll
    for (int off = 16; off > 0; off >>= 1)
        mx = fmaxf(mx, __shfl_xor_sync(0xffffffffu, mx, off));

    float sum = 0.f;
#pragma unroll
    for (int it = 0; it < 5; ++it) {
        int c = lane * 4 + it * 128;
        if (c < SS) {
            v[it].x = expf(v[it].x - mx);
            v[it].y = expf(v[it].y - mx);
            v[it].z = expf(v[it].z - mx);
            v[it].w = expf(v[it].w - mx);
            sum += v[it].x + v[it].y + v[it].z + v[it].w;
        }
    }
#pragma unroll
    for (int off = 16; off > 0; off >>= 1)
        sum += __shfl_xor_sync(0xffffffffu, sum, off);
    float inv = 1.f / sum;

#pragma unroll
    for (int it = 0; it < 5; ++it) {
        int c = lane * 4 + it * 128;
        if (c < SS) {
            __half h[4];
            h[0] = __float2half_rn(v[it].x * inv);
            h[1] = __float2half_rn(v[it].y * inv);
            h[2] = __float2half_rn(v[it].z * inv);
            h[3] = __float2half_rn(v[it].w * inv);
            *(uint2*)&out[c] = *(uint2*)h;
        } else if (c < KPH) {
            *(uint2*)&out[c] = make_uint2(0, 0);
        }
    }
}

// ---------------- host driver ------------------------------------------------
static float* sym_addr_f(const void* sym)
{
    void* p = nullptr;
    cudaGetSymbolAddress(&p, sym);
    return (float*)p;
}
static __half* sym_addr_h(const void* sym)
{
    void* p = nullptr;
    cudaGetSymbolAddress(&p, sym);
    return (__half*)p;
}

extern "C" void kernel_launch(void* const* d_in, const int* in_sizes, int n_in,
                              void* d_out, int out_size)
{
    const float* x   = (const float*)d_in[0];
    const float* W0  = (const float*)d_in[5];
    const float* W1  = (const float*)d_in[6];
    const float* b1  = (const float*)d_in[7];
    const float* W2  = (const float*)d_in[8];
    const float* b2  = (const float*)d_in[9];
    float* out = (float*)d_out;

    float* Wx   = sym_addr_f(g_Wx);
    float* Praw = sym_addr_f(g_Praw);
    float* g1   = sym_addr_f(g_g1);
    float* n1buf[2] = { sym_addr_f(g_n1a), sym_addr_f(g_n1b) };
    float* n2buf[2] = { sym_addr_f(g_n2a), sym_addr_f(g_n2b) };
    __half* xh   = sym_addr_h(g_xh);
    __half* xTh  = sym_addr_h(g_xTh);
    __half* g0h  = sym_addr_h(g_g0h);
    __half* Ph   = sym_addr_h(g_Ph);
    __half* W0h  = sym_addr_h(g_W0h);
    __half* n0h  = sym_addr_h(g_n0h);
    __half* n1h  = sym_addr_h(g_n1h);

    const float scale = 1.0f / sqrtf((float)EE);

    // one-time conversions (x + W0 merged)
    {
        dim3 g(640 + EE, BB);
        conv_inputs_kernel<<<g, 320>>>(x, W0, xh, xTh, W0h);
    }

    // Wx = x @ W0^T; epilogue also emits g0h = fp16(scale*Wx) for step 0
    {
        dim3 grid(3, 75, 1);
        hmma_gemm_kernel<<<grid, 256>>>(
            xh, W0h, Wx, g0h,
            KAH, 0, BB * SS,
            KAH, 0, EE,
            EE, 0, BB * SS, EE,
            KAH, scale,
            10);
    }

    const float* n1c = nullptr;
    const float* n2c = nullptr;

    for (int step = 0; step < TT; ++step) {
        float* n1n = n1buf[step & 1];
        float* n2n = n2buf[step & 1];

        if (step == 0) {
            init_step0_kernel<<<BB, HH>>>(b1, b2, n1n, n2n, n1h);
        } else {
            g2_kernel<<<1, 1024>>>(n1c, W2, b2, n2n);
            // fused: g0h, g1 accumulation, and n1 update (last-block epilogue)
            fused_w1_kernel<<<NDBLK, 256>>>(W1, n1h, n0h, Wx, g1, g0h,
                                            b1, W2, n2c, n1n, n1h, scale);
        }

        // scores = (scale*g0) @ x^T
        {
            dim3 grid(5, 5, BB);
            hmma_gemm_kernel<<<grid, 256>>>(
                g0h, xh, Praw, nullptr,
                KAH, (long)SS * KAH, SS,
                KAH, (long)SS * KAH, SS,
                SS, (long)SS * SS, SS, SS,
                0, 1.0f,
                10);
        }
        softmax_conv_kernel<<<BB * SS / 8, 256>>>(Praw, Ph);
        // n0 = P @ x: steps 0,1 emit only fp16 n0h; final step writes fp32 to d_out
        {
            dim3 grid(3, 5, BB);
            float* cdst = (step == TT - 1) ? out : nullptr;
            __half* hdst = (step == TT - 1) ? nullptr : n0h;
            hmma_gemm_kernel<<<grid, 256>>>(
                Ph, xTh, cdst, hdst,
                KPH, (long)SS * KPH, SS,
                KPH, (long)320 * KPH, 320,
                EE, (long)SS * EE, SS, EE,
                EE, 1.0f,
                20);
        }

        n1c = n1n; n2c = n2n;
    }

    // append n1 | n2 after n0 (n0 already written directly by the last PV GEMM)
    cudaMemcpyAsync(out + (long)BB * SS * EE, n1c, (size_t)BB * HH * sizeof(float),
                    cudaMemcpyDeviceToDevice, 0);
    cudaMemcpyAsync(out + (long)BB * SS * EE + BB * HH, n2c,
                    (size_t)BB * NCC * sizeof(float), cudaMemcpyDeviceToDevice, 0);
}

// round 16
// speedup vs baseline: 1.1459x; 1.1459x over previous
#include <cuda_runtime.h>
#include <cuda_fp16.h>
#include <math.h>
#include <stdint.h>

// Problem constants
#define BB   16
#define SS   600
#define EE   300
#define HH   512
#define NCC  2
#define DD   180000L
#define TT   3

#define KAH  320
#define KPH  640

// fused W1 kernel tiling. PROTECTED: DSLICE=320 @ 2 CTA/SM, simple launch-per-
// step termination (R13 win). R10: never shrink tile. R14: never add
// grid-completion fences/epilogues here.
#define DSLICE 320
#define HCHUNK 32
#define NCHUNK (HH / HCHUNK)
#define NDBLK  ((int)((DD + DSLICE - 1) / DSLICE))   // 563

// ---------------- scratch (device globals; zero-initialized) -----------------
__device__ float g_Wx [BB * SS * EE];
__device__ float g_Praw[BB * SS * SS];
__device__ float g_n1a[BB * HH];
__device__ float g_n1b[BB * HH];
__device__ float g_n2a[BB * NCC];
__device__ float g_n2b[BB * NCC];
__device__ float g_g1 [BB * HH];
__device__ __half g_xh  [(size_t)BB * SS * KAH];
__device__ __half g_xTh [(size_t)BB * 320 * KPH];
__device__ __half g_g0h [(size_t)BB * SS * KAH];
__device__ __half g_Ph  [(size_t)BB * SS * KPH];
__device__ __half g_W0h [(size_t)EE * KAH];
__device__ __half g_n0h [(size_t)BB * DD + 1024];
__device__ __half g_n1h [BB * HH];

// ---------------- helpers -----------------------------------------------------
__device__ __forceinline__ uint32_t smem_u32(const void* p) {
    uint32_t a;
    asm("{ .reg .u64 t; cvta.to.shared.u64 t, %1; cvt.u32.u64 %0, t; }" : "=r"(a) : "l"(p));
    return a;
}
__device__ __forceinline__ void ldm_x4(uint32_t* r, uint32_t addr) {
    asm volatile("ldmatrix.sync.aligned.m8n8.x4.shared.b16 {%0,%1,%2,%3}, [%4];"
                 : "=r"(r[0]), "=r"(r[1]), "=r"(r[2]), "=r"(r[3]) : "r"(addr));
}
__device__ __forceinline__ void ldm_x4_t(uint32_t* r, uint32_t addr) {
    asm volatile("ldmatrix.sync.aligned.m8n8.x4.trans.shared.b16 {%0,%1,%2,%3}, [%4];"
                 : "=r"(r[0]), "=r"(r[1]), "=r"(r[2]), "=r"(r[3]) : "r"(addr));
}
__device__ __forceinline__ void mma16816(float* c, const uint32_t* a, const uint32_t* b) {
    asm volatile(
        "mma.sync.aligned.m16n8k16.row.col.f32.f16.f16.f32 "
        "{%0,%1,%2,%3}, {%4,%5,%6,%7}, {%8,%9}, {%0,%1,%2,%3};"
        : "+f"(c[0]), "+f"(c[1]), "+f"(c[2]), "+f"(c[3])
        : "r"(a[0]), "r"(a[1]), "r"(a[2]), "r"(a[3]), "r"(b[0]), "r"(b[1]));
}
__device__ __forceinline__ void cp_async16(uint32_t dst, const void* src, int bytes) {
    asm volatile("cp.async.cg.shared.global [%0], [%1], 16, %2;"
                 :: "r"(dst), "l"(src), "r"(bytes));
}
__device__ __forceinline__ void cp_commit() {
    asm volatile("cp.async.commit_group;");
}
template <int N>
__device__ __forceinline__ void cp_wait() {
    asm volatile("cp.async.wait_group %0;" :: "n"(N));
}

// ============ fused per-step W1 kernel (R13-proven, DO NOT MODIFY) ===========
// Streams W1 (fp32) once per step:
//   g0h <- fp16((Wx + n1 @ W1) * scale)
//   g1  += n0flat @ W1^T  (g1 pre-initialized with bias by pre_w1_kernel)
__global__ __launch_bounds__(256, 2)
void fused_w1_kernel(const float* __restrict__ W1,
                     const __half* __restrict__ n1h,
                     const __half* __restrict__ n0h,
                     const float* __restrict__ Wx,
                     float* __restrict__ g1,
                     __half* __restrict__ g0h,
                     float scale)
{
    __shared__ __align__(16) __half tF[HCHUNK][DSLICE + 8];
    __shared__ float g1buf[HCHUNK][17];

    const int t = threadIdx.x, lane = t & 31, wid = t >> 5;
    const long d0 = (long)blockIdx.x * DSLICE;

    uint4 pre[10];

    auto issue_loads = [&](int hc) {
#pragma unroll
        for (int i = 0; i < 10; ++i) {
            int f = t + i * 256;
            int row = f / 80, c4 = f % 80;
            long d = d0 + (long)c4 * 4;
            if (d + 4 <= DD)
                pre[i] = *(const uint4*)(W1 + (long)(hc * HCHUNK + row) * DD + d);
            else
                pre[i] = make_uint4(0, 0, 0, 0);
        }
    };
    auto store_tiles = [&]() {
#pragma unroll
        for (int i = 0; i < 10; ++i) {
            int f = t + i * 256;
            int row = f / 80, c4 = f % 80;
            float4 v = *(float4*)&pre[i];
            __half h[4];
            h[0] = __float2half_rn(v.x);
            h[1] = __float2half_rn(v.y);
            h[2] = __float2half_rn(v.z);
            h[3] = __float2half_rn(v.w);
            *(uint2*)&tF[row][c4 * 4] = *(uint2*)h;
        }
    };

    float accg0[10][4] = {};

    issue_loads(0);
    store_tiles();
    for (int i = t; i < HCHUNK * 17; i += 256) ((float*)g1buf)[i] = 0.f;
    __syncthreads();

    for (int hc = 0; hc < NCHUNK; ++hc) {
        if (hc + 1 < NCHUNK) issue_loads(hc + 1);

        if (wid < 4) {
            const int tr_r = lane & 15, tr_c = (lane >> 4) * 8;
            const int ar = lane >> 2, ac = (lane & 3) * 2;
#pragma unroll
            for (int ks = 0; ks < 2; ++ks) {
                int kb = hc * HCHUNK + ks * 16;
                uint32_t ah[4];
                ah[0] = *(const uint32_t*)(n1h + ar * HH + kb + ac);
                ah[1] = *(const uint32_t*)(n1h + (ar + 8) * HH + kb + ac);
                ah[2] = *(const uint32_t*)(n1h + ar * HH + kb + ac + 8);
                ah[3] = *(const uint32_t*)(n1h + (ar + 8) * HH + kb + ac + 8);
#pragma unroll
                for (int q = 0; q < 5; ++q) {
                    uint32_t bf[4];
                    ldm_x4_t(bf, smem_u32(&tF[ks * 16 + tr_r][wid * 80 + q * 16 + tr_c]));
                    mma16816(accg0[q * 2],     ah, &bf[0]);
                    mma16816(accg0[q * 2 + 1], ah, &bf[2]);
                }
            }
        } else {
            const int w = wid - 4;
            const int a_r = lane & 15, a_c = (lane >> 4) * 8;
            float acc1[2][2][4] = {};
#pragma unroll
            for (int ks = 0; ks < 5; ++ks) {
                long dk = d0 + w * 80 + ks * 16;
                uint32_t bh[2][2];
#pragma unroll
                for (int nt = 0; nt < 2; ++nt) {
                    long baddr = (long)(nt * 8 + (lane >> 2)) * DD + dk + (lane & 3) * 2;
                    bh[nt][0] = *(const uint32_t*)(n0h + baddr);
                    bh[nt][1] = *(const uint32_t*)(n0h + baddr + 8);
                }
#pragma unroll
                for (int mt = 0; mt < 2; ++mt) {
                    uint32_t af[4];
                    ldm_x4(af, smem_u32(&tF[mt * 16 + a_r][w * 80 + ks * 16 + a_c]));
#pragma unroll
                    for (int nt = 0; nt < 2; ++nt)
                        mma16816(acc1[mt][nt], af, bh[nt]);
                }
            }
            const int cr = lane >> 2, cc = (lane & 3) * 2;
#pragma unroll
            for (int mt = 0; mt < 2; ++mt)
#pragma unroll
                for (int nt = 0; nt < 2; ++nt) {
                    atomicAdd(&g1buf[mt * 16 + cr][nt * 8 + cc],         acc1[mt][nt][0]);
                    atomicAdd(&g1buf[mt * 16 + cr][nt * 8 + cc + 1],     acc1[mt][nt][1]);
                    atomicAdd(&g1buf[mt * 16 + cr + 8][nt * 8 + cc],     acc1[mt][nt][2]);
                    atomicAdd(&g1buf[mt * 16 + cr + 8][nt * 8 + cc + 1], acc1[mt][nt][3]);
                }
        }
        __syncthreads();

#pragma unroll
        for (int i = 0; i < 2; ++i) {
            int idx = t + i * 256;
            int h = idx >> 4, b = idx & 15;
            float v = g1buf[h][b];
            if (v != 0.f) atomicAdd(&g1[b * HH + hc * HCHUNK + h], v);
            g1buf[h][b] = 0.f;
        }
        if (hc + 1 < NCHUNK) store_tiles();
        __syncthreads();
    }

    // g0 epilogue: (Wx + acc) * scale -> fp16
    if (wid < 4) {
        const int ar = lane >> 2, cc = (lane & 3) * 2;
#pragma unroll
        for (int q = 0; q < 10; ++q) {
            int dn = wid * 80 + q * 8 + cc;
            long d = d0 + dn;
            if (d + 1 < DD) {
                int s = (int)(d / EE), e = (int)(d % EE);
#pragma unroll
                for (int half = 0; half < 2; ++half) {
                    int bb = ar + half * 8;
                    float2 wx = *(const float2*)(Wx + (long)bb * DD + d);
                    __half h[2];
                    h[0] = __float2half_rn((wx.x + accg0[q][half * 2])     * scale);
                    h[1] = __float2half_rn((wx.y + accg0[q][half * 2 + 1]) * scale);
                    *(uint32_t*)&g0h[((long)(bb * SS + s)) * KAH + e] = *(uint32_t*)h;
                }
            }
        }
    }
}

// ---------------- pipelined HMMA GEMM (fp16): C = A · B^T --------------------
__global__ __launch_bounds__(256, 2)
void hmma_gemm_kernel(const __half* __restrict__ A,
                      const __half* __restrict__ B,
                      float* __restrict__ C,
                      __half* __restrict__ Ch,
                      int ldA, long bsA, int rowsA,
                      int ldB, long bsB, int rowsB,
                      int ldC, long bsC, int Mvalid, int Nvalid,
                      int ldCh, float ch_scale,
                      int kchunks)
{
    __shared__ __align__(16) __half As[2][128][40];
    __shared__ __align__(16) __half Bs[2][128][40];
    const int t = threadIdx.x, lane = t & 31, wid = t >> 5;
    const int wm = wid >> 2, wn = wid & 3;
    const int b = blockIdx.z, m0 = blockIdx.y * 128, n0 = blockIdx.x * 128;
    const __half* Ab = A + (long)b * bsA;
    const __half* Bb = B + (long)b * bsB;
    float acc[4][4][4] = {};

    const int l_row = t >> 2, l_q = t & 3;
    auto stage_in = [&](int ch, int buf) {
        long kg = (long)ch * 32 + l_q * 8;
#pragma unroll
        for (int i = 0; i < 2; ++i) {
            int row = l_row + i * 64;
            int ra = m0 + row, rb = n0 + row;
            int ca = (ra < rowsA) ? 16 : 0;
            int cb = (rb < rowsB) ? 16 : 0;
            if (ra >= rowsA) ra = 0;
            if (rb >= rowsB) rb = 0;
            cp_async16(smem_u32(&As[buf][row][l_q * 8]), Ab + (long)ra * ldA + kg, ca);
            cp_async16(smem_u32(&Bs[buf][row][l_q * 8]), Bb + (long)rb * ldB + kg, cb);
        }
    };

    stage_in(0, 0); cp_commit();
    if (kchunks > 1) { stage_in(1, 1); }
    cp_commit();

    const int a_lm = lane & 15;
    const int a_lk = (lane >> 4) * 8;
    const int b_ln = (lane & 7) + ((lane >> 4) & 1) * 8;
    const int b_lk = ((lane >> 3) & 1) * 8;

    for (int ch = 0; ch < kchunks; ++ch) {
        const int buf = ch & 1;
        cp_wait<1>();
        __syncthreads();
#pragma unroll
        for (int ks = 0; ks < 2; ++ks) {
            uint32_t af[4][4], bf[4][2];
#pragma unroll
            for (int mf = 0; mf < 4; ++mf)
                ldm_x4(af[mf], smem_u32(&As[buf][wm * 64 + mf * 16 + a_lm][ks * 16 + a_lk]));
#pragma unroll
            for (int nf2 = 0; nf2 < 2; ++nf2) {
                uint32_t r[4];
                ldm_x4(r, smem_u32(&Bs[buf][wn * 32 + nf2 * 16 + b_ln][ks * 16 + b_lk]));
                bf[nf2 * 2][0] = r[0];     bf[nf2 * 2][1] = r[1];
                bf[nf2 * 2 + 1][0] = r[2]; bf[nf2 * 2 + 1][1] = r[3];
            }
#pragma unroll
            for (int mf = 0; mf < 4; ++mf)
#pragma unroll
                for (int nf = 0; nf < 4; ++nf)
                    mma16816(acc[mf][nf], af[mf], bf[nf]);
        }
        __syncthreads();
        if (ch + 2 < kchunks) stage_in(ch + 2, buf);
        cp_commit();
    }

    const int mbase = m0 + wm * 64, nbase = n0 + wn * 32;
#pragma unroll
    for (int mf = 0; mf < 4; ++mf) {
#pragma unroll
        for (int nf = 0; nf < 4; ++nf) {
            int m = mbase + mf * 16 + (lane >> 2);
            int n = nbase + nf * 8 + (lane & 3) * 2;
            if (n < Nvalid) {
#pragma unroll
                for (int half = 0; half < 2; ++half) {
                    int mm = m + half * 8;
                    float v0 = acc[mf][nf][half * 2], v1 = acc[mf][nf][half * 2 + 1];
                    if (mm < Mvalid) {
                        if (C)
                            *(float2*)&C[(long)b * bsC + (long)mm * ldC + n] =
                                make_float2(v0, v1);
                        if (Ch) {
                            __half h[2];
                            h[0] = __float2half_rn(v0 * ch_scale);
                            h[1] = __float2half_rn(v1 * ch_scale);
                            *(uint32_t*)&Ch[(long)b * bsC + (long)mm * ldCh + n] =
                                *(uint32_t*)h;
                        }
                    }
                }
            }
        }
    }
}

// ---------------- conversions (merged x + W0, one-time) ----------------------
__global__ void conv_inputs_kernel(const float* __restrict__ x,
                                   const float* __restrict__ W0,
                                   __half* __restrict__ xh,
                                   __half* __restrict__ xTh,
                                   __half* __restrict__ W0h)
{
    int e = threadIdx.x;
    if (blockIdx.x < 640) {
        int s = blockIdx.x, b = blockIdx.y;
        if (s < SS) {
            float v = (e < EE) ? x[((long)b * SS + s) * EE + e] : 0.f;
            __half h = __float2half_rn(v);
            xh[((long)b * SS + s) * KAH + e] = h;
            xTh[((long)b * 320 + e) * KPH + s] = h;
        } else {
            xTh[((long)b * 320 + e) * KPH + s] = __float2half_rn(0.f);
        }
    } else if (blockIdx.y == 0) {
        int f = blockIdx.x - 640;
        float v = (e < EE) ? W0[f * EE + e] : 0.f;
        W0h[(long)f * KAH + e] = __float2half_rn(v);
    }
}

// ---------------- merged pre-W1 kernel: g1 init + n2 update ------------------
__global__ void pre_w1_kernel(const float* __restrict__ b1, const float* __restrict__ b2,
                              const float* __restrict__ n1c, const float* __restrict__ n2c,
                              const float* __restrict__ W2,
                              float* __restrict__ g1, float* __restrict__ n2n)
{
    __shared__ float s0[512], s1[512];
    int b = blockIdx.x, h = threadIdx.x;
    float w2c0 = W2[h], w2c1 = W2[HH + h];
    g1[b * HH + h] = b1[h] + n2c[b * NCC] * w2c0 + n2c[b * NCC + 1] * w2c1;
    float n1v = n1c[b * HH + h];
    s0[h] = n1v * w2c0;
    s1[h] = n1v * w2c1;
    __syncthreads();
    for (int s = 256; s > 0; s >>= 1) {
        if (h < s) { s0[h] += s0[h + s]; s1[h] += s1[h + s]; }
        __syncthreads();
    }
    if (h == 0) {
        n2n[b * NCC]     = tanhf(b2[0] + s0[0]);
        n2n[b * NCC + 1] = tanhf(b2[1] + s1[0]);
    }
}

__global__ void tanh_n1_kernel(const float* __restrict__ g1, float* __restrict__ n1n,
                               __half* __restrict__ n1h)
{
    int i = blockIdx.x * blockDim.x + threadIdx.x;
    float v = tanhf(g1[i]);
    n1n[i] = v;
    n1h[i] = __float2half_rn(v);
}

__global__ void init_step0_kernel(const float* __restrict__ b1, const float* __restrict__ b2,
                                  float* __restrict__ n1n, float* __restrict__ n2n,
                                  __half* __restrict__ n1h)
{
    int b = blockIdx.x, h = threadIdx.x;
    float v = tanhf(b1[h]);
    n1n[b * HH + h] = v;
    n1h[b * HH + h] = __float2half_rn(v);
    if (h < NCC) n2n[b * NCC + h] = tanhf(b2[h]);
}

// ---------------- softmax: warp-per-row, fused fp16 conversion ---------------
__global__ __launch_bounds__(256)
void softmax_conv_kernel(const float* __restrict__ Praw, __half* __restrict__ Ph)
{
    const int w = threadIdx.x >> 5, lane = threadIdx.x & 31;
    const long r = (long)blockIdx.x * 8 + w;
    const float* p = Praw + r * SS;
    __half* out = Ph + r * KPH;

    float4 v[5];
    float mx = -INFINITY;
#pragma unroll
    for (int it = 0; it < 5; ++it) {
        int c = lane * 4 + it * 128;
        if (c < SS) {
            v[it] = *(const float4*)(p + c);
            mx = fmaxf(mx, fmaxf(fmaxf(v[it].x, v[it].y), fmaxf(v[it].z, v[it].w)));
        }
    }
#pragma unroll
    for (int off = 16; off > 0; off >>= 1)
        mx = fmaxf(mx, __shfl_xor_sync(0xffffffffu, mx, off));

    float sum = 0.f;
#pragma unroll
    for (int it = 0; it < 5; ++it) {
        int c = lane * 4 + it * 128;
        if (c < SS) {
            v[it].x = expf(v[it].x - mx);
            v[it].y = expf(v[it].y - mx);
            v[it].z = expf(v[it].z - mx);
            v[it].w = expf(v[it].w - mx);
            sum += v[it].x + v[it].y + v[it].z + v[it].w;
        }
    }
#pragma unroll
    for (int off = 16; off > 0; off >>= 1)
        sum += __shfl_xor_sync(0xffffffffu, sum, off);
    float inv = 1.f / sum;

#pragma unroll
    for (int it = 0; it < 5; ++it) {
        int c = lane * 4 + it * 128;
        if (c < SS) {
            __half h[4];
            h[0] = __float2half_rn(v[it].x * inv);
            h[1] = __float2half_rn(v[it].y * inv);
            h[2] = __float2half_rn(v[it].z * inv);
            h[3] = __float2half_rn(v[it].w * inv);
            *(uint2*)&out[c] = *(uint2*)h;
        } else if (c < KPH) {
            *(uint2*)&out[c] = make_uint2(0, 0);
        }
    }
}

// ---------------- host driver ------------------------------------------------
static float* sym_addr_f(const void* sym)
{
    void* p = nullptr;
    cudaGetSymbolAddress(&p, sym);
    return (float*)p;
}
static __half* sym_addr_h(const void* sym)
{
    void* p = nullptr;
    cudaGetSymbolAddress(&p, sym);
    return (__half*)p;
}

extern "C" void kernel_launch(void* const* d_in, const int* in_sizes, int n_in,
                              void* d_out, int out_size)
{
    const float* x   = (const float*)d_in[0];
    const float* W0  = (const float*)d_in[5];
    const float* W1  = (const float*)d_in[6];
    const float* b1  = (const float*)d_in[7];
    const float* W2  = (const float*)d_in[8];
    const float* b2  = (const float*)d_in[9];
    float* out = (float*)d_out;

    float* Wx   = sym_addr_f(g_Wx);
    float* Praw = sym_addr_f(g_Praw);
    float* g1   = sym_addr_f(g_g1);
    float* n1buf[2] = { sym_addr_f(g_n1a), sym_addr_f(g_n1b) };
    float* n2buf[2] = { sym_addr_f(g_n2a), sym_addr_f(g_n2b) };
    __half* xh   = sym_addr_h(g_xh);
    __half* xTh  = sym_addr_h(g_xTh);
    __half* g0h  = sym_addr_h(g_g0h);
    __half* Ph   = sym_addr_h(g_Ph);
    __half* W0h  = sym_addr_h(g_W0h);
    __half* n0h  = sym_addr_h(g_n0h);
    __half* n1h  = sym_addr_h(g_n1h);

    const float scale = 1.0f / sqrtf((float)EE);

    // one-time conversions (x + W0 merged)
    {
        dim3 g(640 + EE, BB);
        conv_inputs_kernel<<<g, 320>>>(x, W0, xh, xTh, W0h);
    }

    // Wx = x @ W0^T; epilogue also emits g0h = fp16(scale*Wx) for step 0
    {
        dim3 grid(3, 75, 1);
        hmma_gemm_kernel<<<grid, 256>>>(
            xh, W0h, Wx, g0h,
            KAH, 0, BB * SS,
            KAH, 0, EE,
            EE, 0, BB * SS, EE,
            KAH, scale,
            10);
    }

    const float* n1c = nullptr;
    const float* n2c = nullptr;

    for (int step = 0; step < TT; ++step) {
        float* n1n = n1buf[step & 1];
        float* n2n = n2buf[step & 1];

        if (step == 0) {
            init_step0_kernel<<<BB, HH>>>(b1, b2, n1n, n2n, n1h);
        } else {
            pre_w1_kernel<<<BB, HH>>>(b1, b2, n1c, n2c, W2, g1, n2n);
            fused_w1_kernel<<<NDBLK, 256>>>(W1, n1h, n0h, Wx, g1, g0h, scale);
            tanh_n1_kernel<<<BB, HH>>>(g1, n1n, n1h);
        }

        // scores = (scale*g0) @ x^T
        {
            dim3 grid(5, 5, BB);
            hmma_gemm_kernel<<<grid, 256>>>(
                g0h, xh, Praw, nullptr,
                KAH, (long)SS * KAH, SS,
                KAH, (long)SS * KAH, SS,
                SS, (long)SS * SS, SS, SS,
                0, 1.0f,
                10);
        }
        softmax_conv_kernel<<<BB * SS / 8, 256>>>(Praw, Ph);
        // n0 = P @ x: steps 0,1 emit only fp16 n0h; final step writes fp32 to d_out
        {
            dim3 grid(3, 5, BB);
            float* cdst = (step == TT - 1) ? out : nullptr;
            __half* hdst = (step == TT - 1) ? nullptr : n0h;
            hmma_gemm_kernel<<<grid, 256>>>(
                Ph, xTh, cdst, hdst,
                KPH, (long)SS * KPH, SS,
                KPH, (long)320 * KPH, 320,
                EE, (long)SS * EE, SS, EE,
                EE, 1.0f,
                20);
        }

        n1c = n1n; n2c = n2n;
    }

    // append n1 | n2 after n0 (n0 already written directly by the last PV GEMM)
    cudaMemcpyAsync(out + (long)BB * SS * EE, n1c, (size_t)BB * HH * sizeof(float),
                    cudaMemcpyDeviceToDevice, 0);
    cudaMemcpyAsync(out + (long)BB * SS * EE + BB * HH, n2c,
                    (size_t)BB * NCC * sizeof(float), cudaMemcpyDeviceToDevice, 0);
}

// round 17
// speedup vs baseline: 1.1460x; 1.0001x over previous
#include <cuda_runtime.h>
#include <cuda_fp16.h>
#include <math.h>
#include <stdint.h>

// Problem constants
#define BB   16
#define SS   600
#define EE   300
#define HH   512
#define NCC  2
#define DD   180000L
#define TT   3

#define KAH  320
#define KPH  640

// fused W1 kernel tiling. PROTECTED: DSLICE=320 @ 2 CTA/SM, simple launch-per-
// step termination (R13 win). R10: never shrink tile. R14: never add
// grid-completion fences/epilogues here.
#define DSLICE 320
#define HCHUNK 32
#define NCHUNK (HH / HCHUNK)
#define NDBLK  ((int)((DD + DSLICE - 1) / DSLICE))   // 563

// ---------------- scratch (device globals; zero-initialized) -----------------
__device__ float g_Praw[BB * SS * SS];
__device__ float g_n1a[BB * HH];
__device__ float g_n1b[BB * HH];
__device__ float g_n2a[BB * NCC];
__device__ float g_n2b[BB * NCC];
__device__ float g_g1 [BB * HH];
__device__ __half g_xh  [(size_t)BB * SS * KAH];
__device__ __half g_xTh [(size_t)BB * 320 * KPH];
__device__ __half g_Wxh [(size_t)BB * SS * KAH];   // fp16(scale*Wx); pads stay 0
__device__ __half g_g0h [(size_t)BB * SS * KAH];
__device__ __half g_Ph  [(size_t)BB * SS * KPH];
__device__ __half g_W0h [(size_t)EE * KAH];
__device__ __half g_n0h [(size_t)BB * DD + 1024];
__device__ __half g_n1h [BB * HH];

// ---------------- helpers -----------------------------------------------------
__device__ __forceinline__ uint32_t smem_u32(const void* p) {
    uint32_t a;
    asm("{ .reg .u64 t; cvta.to.shared.u64 t, %1; cvt.u32.u64 %0, t; }" : "=r"(a) : "l"(p));
    return a;
}
__device__ __forceinline__ void ldm_x4(uint32_t* r, uint32_t addr) {
    asm volatile("ldmatrix.sync.aligned.m8n8.x4.shared.b16 {%0,%1,%2,%3}, [%4];"
                 : "=r"(r[0]), "=r"(r[1]), "=r"(r[2]), "=r"(r[3]) : "r"(addr));
}
__device__ __forceinline__ void ldm_x4_t(uint32_t* r, uint32_t addr) {
    asm volatile("ldmatrix.sync.aligned.m8n8.x4.trans.shared.b16 {%0,%1,%2,%3}, [%4];"
                 : "=r"(r[0]), "=r"(r[1]), "=r"(r[2]), "=r"(r[3]) : "r"(addr));
}
__device__ __forceinline__ void mma16816(float* c, const uint32_t* a, const uint32_t* b) {
    asm volatile(
        "mma.sync.aligned.m16n8k16.row.col.f32.f16.f16.f32 "
        "{%0,%1,%2,%3}, {%4,%5,%6,%7}, {%8,%9}, {%0,%1,%2,%3};"
        : "+f"(c[0]), "+f"(c[1]), "+f"(c[2]), "+f"(c[3])
        : "r"(a[0]), "r"(a[1]), "r"(a[2]), "r"(a[3]), "r"(b[0]), "r"(b[1]));
}
__device__ __forceinline__ void cp_async16(uint32_t dst, const void* src, int bytes) {
    asm volatile("cp.async.cg.shared.global [%0], [%1], 16, %2;"
                 :: "r"(dst), "l"(src), "r"(bytes));
}
__device__ __forceinline__ void cp_commit() {
    asm volatile("cp.async.commit_group;");
}
template <int N>
__device__ __forceinline__ void cp_wait() {
    asm volatile("cp.async.wait_group %0;" :: "n"(N));
}

// ============ fused per-step W1 kernel (R13-proven mainloop) =================
// Streams W1 (fp32) once per step:
//   g0h <- fp16(Wxh + scale*(n1 @ W1))     (Wxh already = fp16(scale*Wx))
//   g1  += n0flat @ W1^T  (g1 pre-initialized with bias by pre_w1_kernel)
__global__ __launch_bounds__(256, 2)
void fused_w1_kernel(const float* __restrict__ W1,
                     const __half* __restrict__ n1h,
                     const __half* __restrict__ n0h,
                     const __half* __restrict__ Wxh,
                     float* __restrict__ g1,
                     __half* __restrict__ g0h,
                     float scale)
{
    __shared__ __align__(16) __half tF[HCHUNK][DSLICE + 8];
    __shared__ float g1buf[HCHUNK][17];

    const int t = threadIdx.x, lane = t & 31, wid = t >> 5;
    const long d0 = (long)blockIdx.x * DSLICE;

    uint4 pre[10];

    auto issue_loads = [&](int hc) {
#pragma unroll
        for (int i = 0; i < 10; ++i) {
            int f = t + i * 256;
            int row = f / 80, c4 = f % 80;
            long d = d0 + (long)c4 * 4;
            if (d + 4 <= DD)
                pre[i] = *(const uint4*)(W1 + (long)(hc * HCHUNK + row) * DD + d);
            else
                pre[i] = make_uint4(0, 0, 0, 0);
        }
    };
    auto store_tiles = [&]() {
#pragma unroll
        for (int i = 0; i < 10; ++i) {
            int f = t + i * 256;
            int row = f / 80, c4 = f % 80;
            float4 v = *(float4*)&pre[i];
            __half h[4];
            h[0] = __float2half_rn(v.x);
            h[1] = __float2half_rn(v.y);
            h[2] = __float2half_rn(v.z);
            h[3] = __float2half_rn(v.w);
            *(uint2*)&tF[row][c4 * 4] = *(uint2*)h;
        }
    };

    float accg0[10][4] = {};

    issue_loads(0);
    store_tiles();
    for (int i = t; i < HCHUNK * 17; i += 256) ((float*)g1buf)[i] = 0.f;
    __syncthreads();

    for (int hc = 0; hc < NCHUNK; ++hc) {
        if (hc + 1 < NCHUNK) issue_loads(hc + 1);

        if (wid < 4) {
            const int tr_r = lane & 15, tr_c = (lane >> 4) * 8;
            const int ar = lane >> 2, ac = (lane & 3) * 2;
#pragma unroll
            for (int ks = 0; ks < 2; ++ks) {
                int kb = hc * HCHUNK + ks * 16;
                uint32_t ah[4];
                ah[0] = *(const uint32_t*)(n1h + ar * HH + kb + ac);
                ah[1] = *(const uint32_t*)(n1h + (ar + 8) * HH + kb + ac);
                ah[2] = *(const uint32_t*)(n1h + ar * HH + kb + ac + 8);
                ah[3] = *(const uint32_t*)(n1h + (ar + 8) * HH + kb + ac + 8);
#pragma unroll
                for (int q = 0; q < 5; ++q) {
                    uint32_t bf[4];
                    ldm_x4_t(bf, smem_u32(&tF[ks * 16 + tr_r][wid * 80 + q * 16 + tr_c]));
                    mma16816(accg0[q * 2],     ah, &bf[0]);
                    mma16816(accg0[q * 2 + 1], ah, &bf[2]);
                }
            }
        } else {
            const int w = wid - 4;
            const int a_r = lane & 15, a_c = (lane >> 4) * 8;
            float acc1[2][2][4] = {};
#pragma unroll
            for (int ks = 0; ks < 5; ++ks) {
                long dk = d0 + w * 80 + ks * 16;
                uint32_t bh[2][2];
#pragma unroll
                for (int nt = 0; nt < 2; ++nt) {
                    long baddr = (long)(nt * 8 + (lane >> 2)) * DD + dk + (lane & 3) * 2;
                    bh[nt][0] = *(const uint32_t*)(n0h + baddr);
                    bh[nt][1] = *(const uint32_t*)(n0h + baddr + 8);
                }
#pragma unroll
                for (int mt = 0; mt < 2; ++mt) {
                    uint32_t af[4];
                    ldm_x4(af, smem_u32(&tF[mt * 16 + a_r][w * 80 + ks * 16 + a_c]));
#pragma unroll
                    for (int nt = 0; nt < 2; ++nt)
                        mma16816(acc1[mt][nt], af, bh[nt]);
                }
            }
            const int cr = lane >> 2, cc = (lane & 3) * 2;
#pragma unroll
            for (int mt = 0; mt < 2; ++mt)
#pragma unroll
                for (int nt = 0; nt < 2; ++nt) {
                    atomicAdd(&g1buf[mt * 16 + cr][nt * 8 + cc],         acc1[mt][nt][0]);
                    atomicAdd(&g1buf[mt * 16 + cr][nt * 8 + cc + 1],     acc1[mt][nt][1]);
                    atomicAdd(&g1buf[mt * 16 + cr + 8][nt * 8 + cc],     acc1[mt][nt][2]);
                    atomicAdd(&g1buf[mt * 16 + cr + 8][nt * 8 + cc + 1], acc1[mt][nt][3]);
                }
        }
        __syncthreads();

#pragma unroll
        for (int i = 0; i < 2; ++i) {
            int idx = t + i * 256;
            int h = idx >> 4, b = idx & 15;
            float v = g1buf[h][b];
            if (v != 0.f) atomicAdd(&g1[b * HH + hc * HCHUNK + h], v);
            g1buf[h][b] = 0.f;
        }
        if (hc + 1 < NCHUNK) store_tiles();
        __syncthreads();
    }

    // g0 epilogue: Wxh + scale*acc -> fp16 (Wxh already carries the scale)
    if (wid < 4) {
        const int ar = lane >> 2, cc = (lane & 3) * 2;
#pragma unroll
        for (int q = 0; q < 10; ++q) {
            int dn = wid * 80 + q * 8 + cc;
            long d = d0 + dn;
            if (d + 1 < DD) {
                int s = (int)(d / EE), e = (int)(d % EE);   // d even -> e even, pair in-row
#pragma unroll
                for (int half = 0; half < 2; ++half) {
                    int bb = ar + half * 8;
                    long rowo = ((long)(bb * SS + s)) * KAH + e;
                    __half2 wx = *(const __half2*)&Wxh[rowo];
                    __half h[2];
                    h[0] = __float2half_rn(__half2float(wx.x) + scale * accg0[q][half * 2]);
                    h[1] = __float2half_rn(__half2float(wx.y) + scale * accg0[q][half * 2 + 1]);
                    *(uint32_t*)&g0h[rowo] = *(uint32_t*)h;
                }
            }
        }
    }
}

// ---------------- pipelined HMMA GEMM (fp16): C = A · B^T --------------------
__global__ __launch_bounds__(256, 2)
void hmma_gemm_kernel(const __half* __restrict__ A,
                      const __half* __restrict__ B,
                      float* __restrict__ C,
                      __half* __restrict__ Ch,
                      int ldA, long bsA, int rowsA,
                      int ldB, long bsB, int rowsB,
                      int ldC, long bsC, int Mvalid, int Nvalid,
                      int ldCh, float ch_scale,
                      int kchunks)
{
    __shared__ __align__(16) __half As[2][128][40];
    __shared__ __align__(16) __half Bs[2][128][40];
    const int t = threadIdx.x, lane = t & 31, wid = t >> 5;
    const int wm = wid >> 2, wn = wid & 3;
    const int b = blockIdx.z, m0 = blockIdx.y * 128, n0 = blockIdx.x * 128;
    const __half* Ab = A + (long)b * bsA;
    const __half* Bb = B + (long)b * bsB;
    float acc[4][4][4] = {};

    const int l_row = t >> 2, l_q = t & 3;
    auto stage_in = [&](int ch, int buf) {
        long kg = (long)ch * 32 + l_q * 8;
#pragma unroll
        for (int i = 0; i < 2; ++i) {
            int row = l_row + i * 64;
            int ra = m0 + row, rb = n0 + row;
            int ca = (ra < rowsA) ? 16 : 0;
            int cb = (rb < rowsB) ? 16 : 0;
            if (ra >= rowsA) ra = 0;
            if (rb >= rowsB) rb = 0;
            cp_async16(smem_u32(&As[buf][row][l_q * 8]), Ab + (long)ra * ldA + kg, ca);
            cp_async16(smem_u32(&Bs[buf][row][l_q * 8]), Bb + (long)rb * ldB + kg, cb);
        }
    };

    stage_in(0, 0); cp_commit();
    if (kchunks > 1) { stage_in(1, 1); }
    cp_commit();

    const int a_lm = lane & 15;
    const int a_lk = (lane >> 4) * 8;
    const int b_ln = (lane & 7) + ((lane >> 4) & 1) * 8;
    const int b_lk = ((lane >> 3) & 1) * 8;

    for (int ch = 0; ch < kchunks; ++ch) {
        const int buf = ch & 1;
        cp_wait<1>();
        __syncthreads();
#pragma unroll
        for (int ks = 0; ks < 2; ++ks) {
            uint32_t af[4][4], bf[4][2];
#pragma unroll
            for (int mf = 0; mf < 4; ++mf)
                ldm_x4(af[mf], smem_u32(&As[buf][wm * 64 + mf * 16 + a_lm][ks * 16 + a_lk]));
#pragma unroll
            for (int nf2 = 0; nf2 < 2; ++nf2) {
                uint32_t r[4];
                ldm_x4(r, smem_u32(&Bs[buf][wn * 32 + nf2 * 16 + b_ln][ks * 16 + b_lk]));
                bf[nf2 * 2][0] = r[0];     bf[nf2 * 2][1] = r[1];
                bf[nf2 * 2 + 1][0] = r[2]; bf[nf2 * 2 + 1][1] = r[3];
            }
#pragma unroll
            for (int mf = 0; mf < 4; ++mf)
#pragma unroll
                for (int nf = 0; nf < 4; ++nf)
                    mma16816(acc[mf][nf], af[mf], bf[nf]);
        }
        __syncthreads();
        if (ch + 2 < kchunks) stage_in(ch + 2, buf);
        cp_commit();
    }

    const int mbase = m0 + wm * 64, nbase = n0 + wn * 32;
#pragma unroll
    for (int mf = 0; mf < 4; ++mf) {
#pragma unroll
        for (int nf = 0; nf < 4; ++nf) {
            int m = mbase + mf * 16 + (lane >> 2);
            int n = nbase + nf * 8 + (lane & 3) * 2;
            if (n < Nvalid) {
#pragma unroll
                for (int half = 0; half < 2; ++half) {
                    int mm = m + half * 8;
                    float v0 = acc[mf][nf][half * 2], v1 = acc[mf][nf][half * 2 + 1];
                    if (mm < Mvalid) {
                        if (C)
                            *(float2*)&C[(long)b * bsC + (long)mm * ldC + n] =
                                make_float2(v0, v1);
                        if (Ch) {
                            __half h[2];
                            h[0] = __float2half_rn(v0 * ch_scale);
                            h[1] = __float2half_rn(v1 * ch_scale);
                            *(uint32_t*)&Ch[(long)b * bsC + (long)mm * ldCh + n] =
                                *(uint32_t*)h;
                        }
                    }
                }
            }
        }
    }
}

// ---------------- conversions (merged x + W0, one-time) ----------------------
__global__ void conv_inputs_kernel(const float* __restrict__ x,
                                   const float* __restrict__ W0,
                                   __half* __restrict__ xh,
                                   __half* __restrict__ xTh,
                                   __half* __restrict__ W0h)
{
    int e = threadIdx.x;
    if (blockIdx.x < 640) {
        int s = blockIdx.x, b = blockIdx.y;
        if (s < SS) {
            float v = (e < EE) ? x[((long)b * SS + s) * EE + e] : 0.f;
            __half h = __float2half_rn(v);
            xh[((long)b * SS + s) * KAH + e] = h;
            xTh[((long)b * 320 + e) * KPH + s] = h;
        } else {
            xTh[((long)b * 320 + e) * KPH + s] = __float2half_rn(0.f);
        }
    } else if (blockIdx.y == 0) {
        int f = blockIdx.x - 640;
        float v = (e < EE) ? W0[f * EE + e] : 0.f;
        W0h[(long)f * KAH + e] = __float2half_rn(v);
    }
}

// ---------------- merged pre-W1 kernel: g1 init + n2 update ------------------
__global__ void pre_w1_kernel(const float* __restrict__ b1, const float* __restrict__ b2,
                              const float* __restrict__ n1c, const float* __restrict__ n2c,
                              const float* __restrict__ W2,
                              float* __restrict__ g1, float* __restrict__ n2n)
{
    __shared__ float s0[512], s1[512];
    int b = blockIdx.x, h = threadIdx.x;
    float w2c0 = W2[h], w2c1 = W2[HH + h];
    g1[b * HH + h] = b1[h] + n2c[b * NCC] * w2c0 + n2c[b * NCC + 1] * w2c1;
    float n1v = n1c[b * HH + h];
    s0[h] = n1v * w2c0;
    s1[h] = n1v * w2c1;
    __syncthreads();
    for (int s = 256; s > 0; s >>= 1) {
        if (h < s) { s0[h] += s0[h + s]; s1[h] += s1[h + s]; }
        __syncthreads();
    }
    if (h == 0) {
        n2n[b * NCC]     = tanhf(b2[0] + s0[0]);
        n2n[b * NCC + 1] = tanhf(b2[1] + s1[0]);
    }
}

__global__ void tanh_n1_kernel(const float* __restrict__ g1, float* __restrict__ n1n,
                               __half* __restrict__ n1h)
{
    int i = blockIdx.x * blockDim.x + threadIdx.x;
    float v = tanhf(g1[i]);
    n1n[i] = v;
    n1h[i] = __float2half_rn(v);
}

__global__ void init_step0_kernel(const float* __restrict__ b1, const float* __restrict__ b2,
                                  float* __restrict__ n1n, float* __restrict__ n2n,
                                  __half* __restrict__ n1h)
{
    int b = blockIdx.x, h = threadIdx.x;
    float v = tanhf(b1[h]);
    n1n[b * HH + h] = v;
    n1h[b * HH + h] = __float2half_rn(v);
    if (h < NCC) n2n[b * NCC + h] = tanhf(b2[h]);
}

// ---------------- softmax: warp-per-row, fused fp16 conversion ---------------
__global__ __launch_bounds__(256)
void softmax_conv_kernel(const float* __restrict__ Praw, __half* __restrict__ Ph)
{
    const int w = threadIdx.x >> 5, lane = threadIdx.x & 31;
    const long r = (long)blockIdx.x * 8 + w;
    const float* p = Praw + r * SS;
    __half* out = Ph + r * KPH;

    float4 v[5];
    float mx = -INFINITY;
#pragma unroll
    for (int it = 0; it < 5; ++it) {
        int c = lane * 4 + it * 128;
        if (c < SS) {
            v[it] = *(const float4*)(p + c);
            mx = fmaxf(mx, fmaxf(fmaxf(v[it].x, v[it].y), fmaxf(v[it].z, v[it].w)));
        }
    }
#pragma unroll
    for (int off = 16; off > 0; off >>= 1)
        mx = fmaxf(mx, __shfl_xor_sync(0xffffffffu, mx, off));

    float sum = 0.f;
#pragma unroll
    for (int it = 0; it < 5; ++it) {
        int c = lane * 4 + it * 128;
        if (c < SS) {
            v[it].x = expf(v[it].x - mx);
            v[it].y = expf(v[it].y - mx);
            v[it].z = expf(v[it].z - mx);
            v[it].w = expf(v[it].w - mx);
            sum += v[it].x + v[it].y + v[it].z + v[it].w;
        }
    }
#pragma unroll
    for (int off = 16; off > 0; off >>= 1)
        sum += __shfl_xor_sync(0xffffffffu, sum, off);
    float inv = 1.f / sum;

#pragma unroll
    for (int it = 0; it < 5; ++it) {
        int c = lane * 4 + it * 128;
        if (c < SS) {
            __half h[4];
            h[0] = __float2half_rn(v[it].x * inv);
            h[1] = __float2half_rn(v[it].y * inv);
            h[2] = __float2half_rn(v[it].z * inv);
            h[3] = __float2half_rn(v[it].w * inv);
            *(uint2*)&out[c] = *(uint2*)h;
        } else if (c < KPH) {
            *(uint2*)&out[c] = make_uint2(0, 0);
        }
    }
}

// ---------------- host driver ------------------------------------------------
static float* sym_addr_f(const void* sym)
{
    void* p = nullptr;
    cudaGetSymbolAddress(&p, sym);
    return (float*)p;
}
static __half* sym_addr_h(const void* sym)
{
    void* p = nullptr;
    cudaGetSymbolAddress(&p, sym);
    return (__half*)p;
}

extern "C" void kernel_launch(void* const* d_in, const int* in_sizes, int n_in,
                              void* d_out, int out_size)
{
    const float* x   = (const float*)d_in[0];
    const float* W0  = (const float*)d_in[5];
    const float* W1  = (const float*)d_in[6];
    const float* b1  = (const float*)d_in[7];
    const float* W2  = (const float*)d_in[8];
    const float* b2  = (const float*)d_in[9];
    float* out = (float*)d_out;

    float* Praw = sym_addr_f(g_Praw);
    float* g1   = sym_addr_f(g_g1);
    float* n1buf[2] = { sym_addr_f(g_n1a), sym_addr_f(g_n1b) };
    float* n2buf[2] = { sym_addr_f(g_n2a), sym_addr_f(g_n2b) };
    __half* xh   = sym_addr_h(g_xh);
    __half* xTh  = sym_addr_h(g_xTh);
    __half* Wxh  = sym_addr_h(g_Wxh);
    __half* g0h  = sym_addr_h(g_g0h);
    __half* Ph   = sym_addr_h(g_Ph);
    __half* W0h  = sym_addr_h(g_W0h);
    __half* n0h  = sym_addr_h(g_n0h);
    __half* n1h  = sym_addr_h(g_n1h);

    const float scale = 1.0f / sqrtf((float)EE);

    // one-time conversions (x + W0 merged)
    {
        dim3 g(640 + EE, BB);
        conv_inputs_kernel<<<g, 320>>>(x, W0, xh, xTh, W0h);
    }

    // Wxh = fp16(scale * (x @ W0^T))  — fp16-only epilogue, no fp32 store
    {
        dim3 grid(3, 75, 1);
        hmma_gemm_kernel<<<grid, 256>>>(
            xh, W0h, nullptr, Wxh,
            KAH, 0, BB * SS,
            KAH, 0, EE,
            EE, 0, BB * SS, EE,
            KAH, scale,
            10);
    }

    const float* n1c = nullptr;
    const float* n2c = nullptr;

    for (int step = 0; step < TT; ++step) {
        float* n1n = n1buf[step & 1];
        float* n2n = n2buf[step & 1];

        if (step == 0) {
            init_step0_kernel<<<BB, HH>>>(b1, b2, n1n, n2n, n1h);
        } else {
            pre_w1_kernel<<<BB, HH>>>(b1, b2, n1c, n2c, W2, g1, n2n);
            fused_w1_kernel<<<NDBLK, 256>>>(W1, n1h, n0h, Wxh, g1, g0h, scale);
            tanh_n1_kernel<<<BB, HH>>>(g1, n1n, n1h);
        }

        // scores = (scale*g0) @ x^T   (step 0: g0 = Wx, so A = Wxh directly)
        {
            const __half* Ascore = (step == 0) ? Wxh : g0h;
            dim3 grid(5, 5, BB);
            hmma_gemm_kernel<<<grid, 256>>>(
                Ascore, xh, Praw, nullptr,
                KAH, (long)SS * KAH, SS,
                KAH, (long)SS * KAH, SS,
                SS, (long)SS * SS, SS, SS,
                0, 1.0f,
                10);
        }
        softmax_conv_kernel<<<BB * SS / 8, 256>>>(Praw, Ph);
        // n0 = P @ x: steps 0,1 emit only fp16 n0h; final step writes fp32 to d_out
        {
            dim3 grid(3, 5, BB);
            float* cdst = (step == TT - 1) ? out : nullptr;
            __half* hdst = (step == TT - 1) ? nullptr : n0h;
            hmma_gemm_kernel<<<grid, 256>>>(
                Ph, xTh, cdst, hdst,
                KPH, (long)SS * KPH, SS,
                KPH, (long)320 * KPH, 320,
                EE, (long)SS * EE, SS, EE,
                EE, 1.0f,
                20);
        }

        n1c = n1n; n2c = n2n;
    }

    // append n1 | n2 after n0 (n0 already written directly by the last PV GEMM)
    cudaMemcpyAsync(out + (long)BB * SS * EE, n1c, (size_t)BB * HH * sizeof(float),
                    cudaMemcpyDeviceToDevice, 0);
    cudaMemcpyAsync(out + (long)BB * SS * EE + BB * HH, n2c,
                    (size_t)BB * NCC * sizeof(float), cudaMemcpyDeviceToDevice, 0);
}